// round 13
// baseline (speedup 1.0000x reference)
#include <cuda_runtime.h>
#include <math.h>

// SE block: B=32, H=W=56 (HW=3136), C=256, R=16, fp32 NHWC.
// out = in * sigmoid(relu(mean_hw(in) @ W1 + b1) @ W2 + b2)
//
// R12: ONE persistent launch. grid = 1184 = 8 blocks/SM x 148 SMs, all
// resident (__launch_bounds__(256,8) -> deadlock-free per-batch spin).
// Block (k,b): pool chunk k of batch b -> per-batch ticket; finisher runs
// excite and releases a flag; all 37 blocks of the batch acquire the flag
// and scale the SAME chunk they pooled (reads hit own L1 / hot L2; only the
// output write stream touches DRAM, st.cs). Counters/flags reset by the
// last participant -> deterministic and graph-replay safe.

#define Bb      32
#define HW      3136
#define Cc      256
#define CR      16
#define KSPLIT  37          // 32*37 = 1184 blocks = 8/SM on 148 SMs
#define CHUNKP  85          // ceil(3136/37); last chunk is 76
#define CQ      64          // C/4 float4 quads per position

__device__ float g_partial[Bb * KSPLIT * Cc];   // ~1.2 MB scratch
__device__ float g_exc[Bb * Cc];                // 32 KB excitation
__device__ int   g_countA[Bb];                  // pool arrivals  (reset by finisher)
__device__ int   g_countB[Bb];                  // scale completions (reset by last)
__device__ int   g_flag[Bb];                    // excitation-ready flag

__device__ __forceinline__ void stg_cs(float4* p, float4 v) {
    asm volatile("st.global.cs.v4.f32 [%0], {%1,%2,%3,%4};"
                 :: "l"(p), "f"(v.x), "f"(v.y), "f"(v.z), "f"(v.w) : "memory");
}

__global__ void __launch_bounds__(256, 8)
se_fused(const float* __restrict__ in,
         const float* __restrict__ W1, const float* __restrict__ b1,
         const float* __restrict__ W2, const float* __restrict__ b2,
         float* __restrict__ out)
{
    const int k   = blockIdx.x;
    const int b   = blockIdx.y;
    const int tid = threadIdx.x;
    const int q   = tid & 63;
    const int pg  = tid >> 6;

    const float4* __restrict__ in4 = reinterpret_cast<const float4*>(in)
                                     + (size_t)b * HW * CQ;

    const int pBeg = k * CHUNKP;
    const int pEnd = (pBeg + CHUNKP < HW) ? (pBeg + CHUNKP) : HW;

    // ================= Phase 1: pool own chunk ==============================
    {
        float4 a0 = make_float4(0.f, 0.f, 0.f, 0.f);
        float4 a1 = make_float4(0.f, 0.f, 0.f, 0.f);
        int p = pBeg + pg;
        for (; p + 4 < pEnd; p += 8) {
            float4 v0 = __ldg(&in4[(size_t)p * CQ + q]);
            float4 v1 = __ldg(&in4[(size_t)(p + 4) * CQ + q]);
            a0.x += v0.x; a0.y += v0.y; a0.z += v0.z; a0.w += v0.w;
            a1.x += v1.x; a1.y += v1.y; a1.z += v1.z; a1.w += v1.w;
        }
        if (p < pEnd) {
            float4 v0 = __ldg(&in4[(size_t)p * CQ + q]);
            a0.x += v0.x; a0.y += v0.y; a0.z += v0.z; a0.w += v0.w;
        }
        a0.x += a1.x; a0.y += a1.y; a0.z += a1.z; a0.w += a1.w;

        __shared__ float4 s4[256];
        s4[tid] = a0;
        __syncthreads();

        if (tid < 64) {
            float4 a = s4[tid];
            float4 c = s4[tid + 64];
            float4 d = s4[tid + 128];
            float4 e = s4[tid + 192];
            float4 r = make_float4(a.x + c.x + d.x + e.x,
                                   a.y + c.y + d.y + e.y,
                                   a.z + c.z + d.z + e.z,
                                   a.w + c.w + d.w + e.w);
            reinterpret_cast<float4*>(g_partial)[(b * KSPLIT + k) * CQ + tid] = r;
        }
        __syncthreads();
    }

    // ================= Phase 2: elect finisher, excite ======================
    __shared__ int sLast;
    if (tid == 0) {
        __threadfence();
        int ticket = atomicAdd(&g_countA[b], 1);
        sLast = (ticket == KSPLIT - 1);
        if (sLast) g_countA[b] = 0;                    // reset for next replay
    }
    __syncthreads();

    if (sLast) {
        __threadfence();                               // see peers' partials
        __shared__ float sq[Cc];
        __shared__ float pj[16][CR + 1];
        __shared__ float hs[CR];

        {
            const float* __restrict__ part = g_partial + (size_t)b * KSPLIT * Cc + tid;
            float sum = 0.f;
            #pragma unroll
            for (int kk = 0; kk < KSPLIT; kk++)
                sum += part[kk * Cc];
            sq[tid] = sum * (1.0f / (float)HW);
        }
        __syncthreads();

        {
            const int j = tid & 15;
            const int g = tid >> 4;
            float h = 0.f;
            #pragma unroll
            for (int i2 = 0; i2 < 16; i2++)
                h = fmaf(sq[g * 16 + i2], __ldg(&W1[(g * 16 + i2) * CR + j]), h);
            pj[g][j] = h;
        }
        __syncthreads();
        if (tid < CR) {
            float h = __ldg(&b1[tid]);
            #pragma unroll
            for (int g2 = 0; g2 < 16; g2++)
                h += pj[g2][tid];
            hs[tid] = fmaxf(h, 0.f);
        }
        __syncthreads();

        float e = __ldg(&b2[tid]);
        #pragma unroll
        for (int j = 0; j < CR; j++)
            e = fmaf(hs[j], __ldg(&W2[j * Cc + tid]), e);
        g_exc[b * Cc + tid] = 1.0f / (1.0f + __expf(-e));

        __threadfence();                               // exc visible GPU-wide
        __syncthreads();
        if (tid == 0)
            asm volatile("st.release.gpu.global.b32 [%0], %1;"
                         :: "l"(&g_flag[b]), "r"(1) : "memory");
    }

    // ================= Phase 3: wait for excitation =========================
    if (tid == 0) {
        int f;
        do {
            asm volatile("ld.acquire.gpu.global.b32 %0, [%1];"
                         : "=r"(f) : "l"(&g_flag[b]) : "memory");
            if (!f) __nanosleep(64);
        } while (!f);
    }
    __syncthreads();

    // ================= Phase 4: scale own chunk (L1/L2-hot reads) ===========
    {
        float4 e;
        asm volatile("ld.global.cg.v4.f32 {%0,%1,%2,%3}, [%4];"
                     : "=f"(e.x), "=f"(e.y), "=f"(e.z), "=f"(e.w)
                     : "l"(reinterpret_cast<const float4*>(g_exc) + b * CQ + q));

        float4* __restrict__ out4 = reinterpret_cast<float4*>(out)
                                    + (size_t)b * HW * CQ;
        int p = pBeg + pg;
        for (; p + 4 < pEnd; p += 8) {
            float4 v0 = __ldg(&in4[(size_t)p * CQ + q]);
            float4 v1 = __ldg(&in4[(size_t)(p + 4) * CQ + q]);
            v0.x *= e.x; v0.y *= e.y; v0.z *= e.z; v0.w *= e.w;
            v1.x *= e.x; v1.y *= e.y; v1.z *= e.z; v1.w *= e.w;
            stg_cs(&out4[(size_t)p * CQ + q],       v0);
            stg_cs(&out4[(size_t)(p + 4) * CQ + q], v1);
        }
        if (p < pEnd) {
            float4 v0 = __ldg(&in4[(size_t)p * CQ + q]);
            v0.x *= e.x; v0.y *= e.y; v0.z *= e.z; v0.w *= e.w;
            stg_cs(&out4[(size_t)p * CQ + q], v0);
        }
    }

    // ================= Phase 5: last scaler resets flag =====================
    __syncthreads();
    if (tid == 0) {
        __threadfence();
        int t = atomicAdd(&g_countB[b], 1);
        if (t == KSPLIT - 1) {
            g_countB[b] = 0;
            g_flag[b]   = 0;                           // ready for next replay
        }
    }
}

// ---------------------------------------------------------------------------
extern "C" void kernel_launch(void* const* d_in, const int* in_sizes, int n_in,
                              void* d_out, int out_size)
{
    const float* in = (const float*)d_in[0];
    const float* W1 = (const float*)d_in[1];
    const float* b1 = (const float*)d_in[2];
    const float* W2 = (const float*)d_in[3];
    const float* b2 = (const float*)d_in[4];
    float* out = (float*)d_out;

    se_fused<<<dim3(KSPLIT, Bb), 256>>>(in, W1, b1, W2, b2, out);  // 1184 blocks
}